// round 14
// baseline (speedup 1.0000x reference)
#include <cuda_runtime.h>
#include <cuda_bf16.h>
#include <cstdint>

#define HNUM 16
#define NSEQ 2048
#define DDIM 64
#define CHK  64
#define NC   (NSEQ / CHK)      // 32 chunks
#define NB   (HNUM * NC)       // 512 (head, chunk) tiles
#define EPSV 1e-6f

// Scratch
__device__ float g_KV[(size_t)NB * DDIM * DDIM];          // per-chunk KV sums (8 MB)
__device__ float g_Kz[(size_t)NB * DDIM];                 // per-chunk colsum -> excl prefix
__device__ __align__(16) uint32_t g_Sh[(size_t)NB * 2048]; // excl-prefix S, bf16 hi (packed bf162)
__device__ __align__(16) uint32_t g_Sl[(size_t)NB * 2048]; // excl-prefix S, bf16 lo

__device__ __forceinline__ float fmap(float x) {
    return x > 0.f ? x + 1.f : __expf(x);
}

// ---- mma helpers ----
__device__ __forceinline__ uint32_t smem_u32(const void* p) {
    return (uint32_t)__cvta_generic_to_shared(p);
}
__device__ __forceinline__ void ldsm_x4(uint32_t a[4], uint32_t addr) {
    asm volatile("ldmatrix.sync.aligned.m8n8.x4.shared.b16 {%0,%1,%2,%3}, [%4];"
                 : "=r"(a[0]), "=r"(a[1]), "=r"(a[2]), "=r"(a[3]) : "r"(addr));
}
__device__ __forceinline__ void ldsm_x4t(uint32_t a[4], uint32_t addr) {
    asm volatile("ldmatrix.sync.aligned.m8n8.x4.trans.shared.b16 {%0,%1,%2,%3}, [%4];"
                 : "=r"(a[0]), "=r"(a[1]), "=r"(a[2]), "=r"(a[3]) : "r"(addr));
}
__device__ __forceinline__ void ldsm_x2t(uint32_t a[2], uint32_t addr) {
    asm volatile("ldmatrix.sync.aligned.m8n8.x2.trans.shared.b16 {%0,%1}, [%2];"
                 : "=r"(a[0]), "=r"(a[1]) : "r"(addr));
}
__device__ __forceinline__ void mma_bf16(float d[4], const uint32_t a[4],
                                         const uint32_t b0, const uint32_t b1) {
    asm volatile(
        "mma.sync.aligned.m16n8k16.row.col.f32.bf16.bf16.f32 "
        "{%0,%1,%2,%3}, {%4,%5,%6,%7}, {%8,%9}, {%0,%1,%2,%3};"
        : "+f"(d[0]), "+f"(d[1]), "+f"(d[2]), "+f"(d[3])
        : "r"(a[0]), "r"(a[1]), "r"(a[2]), "r"(a[3]), "r"(b0), "r"(b1));
}
__device__ __forceinline__ void splitb(float x, __nv_bfloat16& h, __nv_bfloat16& l) {
    h = __float2bfloat16(x);
    l = __float2bfloat16(x - __bfloat162float(h));
}

#define ST2 72
#define TILE_ELEMS (64 * ST2)

// ---------------------------------------------------------------------------
// Phase 1 (tensor-core): KV[d][e] = sum_m phiK[m][d] V[m][e]; aux col V[:,64]=1
// gives col 64 = Kz[d].  [R11 champion verbatim]
// ---------------------------------------------------------------------------
__global__ void __launch_bounds__(256) lin_phase1(const float* __restrict__ Kg,
                                                  const float* __restrict__ Vg) {
    extern __shared__ __nv_bfloat16 smb1[];
    __nv_bfloat16* sKh = smb1;                     // [m][d] row-major
    __nv_bfloat16* sKl = sKh + TILE_ELEMS;
    __nv_bfloat16* sVh = sKl + TILE_ELEMS;         // [m][e], col64 = 1
    __nv_bfloat16* sVl = sVh + TILE_ELEMS;

    const int tid = threadIdx.x;
    const size_t base = (size_t)blockIdx.x * (CHK * DDIM);

    {
        const int m  = tid >> 2;          // 0..63
        const int c0 = (tid & 3) * 16;
        #pragma unroll
        for (int u = 0; u < 4; u++) {
            int col = c0 + 4 * u;
            float4 k = *(const float4*)(Kg + base + m * DDIM + col);
            float4 v = *(const float4*)(Vg + base + m * DDIM + col);
            float kv[4] = {fmap(k.x), fmap(k.y), fmap(k.z), fmap(k.w)};
            float vv[4] = {v.x, v.y, v.z, v.w};
            #pragma unroll
            for (int p = 0; p < 2; p++) {
                __nv_bfloat162 kh2, kl2, vh2, vl2;
                splitb(kv[2*p],   kh2.x, kl2.x);
                splitb(kv[2*p+1], kh2.y, kl2.y);
                splitb(vv[2*p],   vh2.x, vl2.x);
                splitb(vv[2*p+1], vh2.y, vl2.y);
                *(__nv_bfloat162*)&sKh[m * ST2 + col + 2*p] = kh2;
                *(__nv_bfloat162*)&sKl[m * ST2 + col + 2*p] = kl2;
                *(__nv_bfloat162*)&sVh[m * ST2 + col + 2*p] = vh2;
                *(__nv_bfloat162*)&sVl[m * ST2 + col + 2*p] = vl2;
            }
        }
        if (tid < 64) {                            // aux cols 64..71 of V
            sVh[tid * ST2 + 64] = __float2bfloat16(1.0f);
            sVl[tid * ST2 + 64] = __float2bfloat16(0.0f);
            #pragma unroll
            for (int c = 65; c < 72; c++) {
                sVh[tid * ST2 + c] = __float2bfloat16(0.0f);
                sVl[tid * ST2 + c] = __float2bfloat16(0.0f);
            }
        }
    }
    __syncthreads();

    const int w    = tid >> 5;
    const int lane = tid & 31;
    const int g    = lane >> 2;
    const int tig  = lane & 3;
    const int drow = (w >> 1) * 16;
    const int ecol = (w & 1) * 32;
    const int lr   = lane & 7;
    const int lhf  = (lane >> 3) & 1;
    const int lnh  = lane >> 4;
    const bool has_aux = (w & 1);

    float dO[5][4] = {};
    #pragma unroll
    for (int ks = 0; ks < 4; ks++) {
        uint32_t ah[4], al[4];
        ldsm_x4t(ah, smem_u32(&sKh[(ks*16 + lnh*8 + lr) * ST2 + drow + lhf*8]));
        ldsm_x4t(al, smem_u32(&sKl[(ks*16 + lnh*8 + lr) * ST2 + drow + lhf*8]));
        uint32_t bh[4][2], bl[4][2];
        #pragma unroll
        for (int blk = 0; blk < 2; blk++) {
            uint32_t r4[4];
            ldsm_x4t(r4, smem_u32(&sVh[(ks*16 + lhf*8 + lr) * ST2 + ecol + blk*16 + lnh*8]));
            bh[blk*2][0] = r4[0]; bh[blk*2][1] = r4[1];
            bh[blk*2+1][0] = r4[2]; bh[blk*2+1][1] = r4[3];
            ldsm_x4t(r4, smem_u32(&sVl[(ks*16 + lhf*8 + lr) * ST2 + ecol + blk*16 + lnh*8]));
            bl[blk*2][0] = r4[0]; bl[blk*2][1] = r4[1];
            bl[blk*2+1][0] = r4[2]; bl[blk*2+1][1] = r4[3];
        }
        #pragma unroll
        for (int t = 0; t < 4; t++) {
            mma_bf16(dO[t], ah, bh[t][0], bh[t][1]);
            mma_bf16(dO[t], ah, bl[t][0], bl[t][1]);
            mma_bf16(dO[t], al, bh[t][0], bh[t][1]);
        }
        if (has_aux) {
            uint32_t bxh[2], bxl[2];
            int r16 = lane & 15;
            int rr  = (r16 & 7) + ((r16 >> 3) & 1) * 8;
            ldsm_x2t(bxh, smem_u32(&sVh[(ks*16 + rr) * ST2 + 64]));
            ldsm_x2t(bxl, smem_u32(&sVl[(ks*16 + rr) * ST2 + 64]));
            mma_bf16(dO[4], ah, bxh[0], bxh[1]);
            mma_bf16(dO[4], ah, bxl[0], bxl[1]);
            mma_bf16(dO[4], al, bxh[0], bxh[1]);
        }
    }

    float* kvo = g_KV + (size_t)blockIdx.x * (DDIM * DDIM);
    const int row0 = drow + g;
    const int row1 = row0 + 8;
    #pragma unroll
    for (int t = 0; t < 4; t++) {
        int col = ecol + 8*t + 2*tig;
        *(float2*)&kvo[row0 * DDIM + col] = make_float2(dO[t][0], dO[t][1]);
        *(float2*)&kvo[row1 * DDIM + col] = make_float2(dO[t][2], dO[t][3]);
    }
    if (has_aux && tig == 0) {
        g_Kz[(size_t)blockIdx.x * DDIM + row0] = dO[4][0];
        g_Kz[(size_t)blockIdx.x * DDIM + row1] = dO[4][2];
    }
}

// ---------------------------------------------------------------------------
// Phase 2: float4-wide exclusive prefix over 32 chunks per head; writes the
// prefix PRE-SPLIT into bf16 hi/lo arrays (g_Sh/g_Sl).  No fp32 writeback.
// grid = 16 heads * 8 parts = 128, block = 128.
// ---------------------------------------------------------------------------
__global__ void __launch_bounds__(128) lin_phase2() {
    const int h = blockIdx.x >> 3;
    const int part = blockIdx.x & 7;
    const int i4 = part * 128 + threadIdx.x;    // 0..1023 float4 index per tile

    float4 run = make_float4(0.f, 0.f, 0.f, 0.f);
    #pragma unroll
    for (int c = 0; c < NC; c++) {
        const size_t tile = (size_t)(h * NC + c);
        // write EXCLUSIVE prefix, split to bf16 hi/lo (bf162-packed)
        __nv_bfloat162 h0, h1, l0, l1;
        splitb(run.x, h0.x, l0.x); splitb(run.y, h0.y, l0.y);
        splitb(run.z, h1.x, l1.x); splitb(run.w, h1.y, l1.y);
        uint2 hv, lv;
        hv.x = *(uint32_t*)&h0; hv.y = *(uint32_t*)&h1;
        lv.x = *(uint32_t*)&l0; lv.y = *(uint32_t*)&l1;
        *(uint2*)&g_Sh[tile * 2048 + (size_t)i4 * 2] = hv;
        *(uint2*)&g_Sl[tile * 2048 + (size_t)i4 * 2] = lv;

        float4 v = ((const float4*)(g_KV + tile * (DDIM * DDIM)))[i4];
        run.x += v.x; run.y += v.y; run.z += v.z; run.w += v.w;
    }
    if (part == 0 && threadIdx.x < DDIM) {      // z scan (fp32, in place)
        float rz = 0.f;
        #pragma unroll
        for (int c = 0; c < NC; c++) {
            float* p = g_Kz + (size_t)(h * NC + c) * DDIM + threadIdx.x;
            float v = *p;
            *p = rz;
            rz += v;
        }
    }
}

// ---------------------------------------------------------------------------
// Phase 3: tensor-core bf16-split mma, A aliases dead K buffers (74 KB smem).
// THIS ROUND: S arrives pre-split from phase2 -> prologue is raw uint4 copies.
// ---------------------------------------------------------------------------
__global__ void __launch_bounds__(256) lin_phase3(const float* __restrict__ Qg,
                                                  const float* __restrict__ Kg,
                                                  const float* __restrict__ Vg,
                                                  float* __restrict__ Og) {
    extern __shared__ __nv_bfloat16 smb[];
    __nv_bfloat16* sQh = smb;
    __nv_bfloat16* sQl = sQh + TILE_ELEMS;
    __nv_bfloat16* sKh = sQl + TILE_ELEMS;   // [j][d] row-major; becomes sAh
    __nv_bfloat16* sKl = sKh + TILE_ELEMS;   //                  becomes sAl
    __nv_bfloat16* sVh = sKl + TILE_ELEMS;   // [k][e], col64 = 1
    __nv_bfloat16* sVl = sVh + TILE_ELEMS;
    __nv_bfloat16* sSh = sVl + TILE_ELEMS;   // [d][e], col64 = z
    __nv_bfloat16* sSl = sSh + TILE_ELEMS;
    __nv_bfloat16* sAh = sKh;                // alias (K dead after A-phase)
    __nv_bfloat16* sAl = sKl;                // alias
    float* sDen = (float*)(sSl + TILE_ELEMS);

    const int tid = threadIdx.x;
    const size_t base = (size_t)blockIdx.x * (CHK * DDIM);

    // ---------------- load + fmap + split ----------------
    {
        const int m  = tid >> 2;          // 0..63
        const int c0 = (tid & 3) * 16;
        #pragma unroll
        for (int u = 0; u < 4; u++) {
            int col = c0 + 4 * u;
            float4 q = *(const float4*)(Qg + base + m * DDIM + col);
            float4 k = *(const float4*)(Kg + base + m * DDIM + col);
            float4 v = *(const float4*)(Vg + base + m * DDIM + col);
            float qv[4] = {fmap(q.x), fmap(q.y), fmap(q.z), fmap(q.w)};
            float kv[4] = {fmap(k.x), fmap(k.y), fmap(k.z), fmap(k.w)};
            float vv[4] = {v.x, v.y, v.z, v.w};
            #pragma unroll
            for (int p = 0; p < 2; p++) {
                __nv_bfloat162 qh2, ql2, kh2, kl2, vh2, vl2;
                splitb(qv[2*p],   qh2.x, ql2.x);
                splitb(qv[2*p+1], qh2.y, ql2.y);
                splitb(kv[2*p],   kh2.x, kl2.x);
                splitb(kv[2*p+1], kh2.y, kl2.y);
                splitb(vv[2*p],   vh2.x, vl2.x);
                splitb(vv[2*p+1], vh2.y, vl2.y);
                *(__nv_bfloat162*)&sQh[m * ST2 + col + 2*p] = qh2;
                *(__nv_bfloat162*)&sQl[m * ST2 + col + 2*p] = ql2;
                *(__nv_bfloat162*)&sKh[m * ST2 + col + 2*p] = kh2;
                *(__nv_bfloat162*)&sKl[m * ST2 + col + 2*p] = kl2;
                *(__nv_bfloat162*)&sVh[m * ST2 + col + 2*p] = vh2;
                *(__nv_bfloat162*)&sVl[m * ST2 + col + 2*p] = vl2;
            }
        }
        // S pre-split: raw uint4 copies (512 uint4 per array)
        const uint4* Sh4 = (const uint4*)(g_Sh + (size_t)blockIdx.x * 2048);
        const uint4* Sl4 = (const uint4*)(g_Sl + (size_t)blockIdx.x * 2048);
        #pragma unroll
        for (int s = 0; s < 2; s++) {
            int iu = tid + s * 256;       // 0..511
            uint4 hv = Sh4[iu];
            uint4 lv = Sl4[iu];
            int d = iu >> 3;              // 8 uint4 (=32 uint32 = 64 bf16) per row
            int e = (iu & 7) * 8;         // bf16 column
            *(uint4*)&sSh[d * ST2 + e] = hv;
            *(uint4*)&sSl[d * ST2 + e] = lv;
        }
        if (tid < 64) {
            float z = g_Kz[(size_t)blockIdx.x * DDIM + tid];
            __nv_bfloat16 zh, zl;
            splitb(z, zh, zl);
            sSh[tid * ST2 + 64] = zh;
            sSl[tid * ST2 + 64] = zl;
            sVh[tid * ST2 + 64] = __float2bfloat16(1.0f);
            sVl[tid * ST2 + 64] = __float2bfloat16(0.0f);
            #pragma unroll
            for (int c = 65; c < 72; c++) {
                sVh[tid * ST2 + c] = __float2bfloat16(0.0f);
                sVl[tid * ST2 + c] = __float2bfloat16(0.0f);
                sSh[tid * ST2 + c] = __float2bfloat16(0.0f);
                sSl[tid * ST2 + c] = __float2bfloat16(0.0f);
            }
        }
    }
    __syncthreads();

    const int w    = tid >> 5;
    const int lane = tid & 31;
    const int g    = lane >> 2;
    const int tig  = lane & 3;
    const int mrow = (w >> 1) * 16;
    const int jcol = (w & 1) * 32;
    const int lr  = lane & 7;
    const int lhf = (lane >> 3) & 1;
    const int lnh = lane >> 4;

    // ---------------- A-phase: A = phiQ phiK^T (K read, then aliased write) ----------------
    {
        float dA[4][4] = {};
        #pragma unroll
        for (int ks = 0; ks < 4; ks++) {
            uint32_t ah[4], al[4];
            ldsm_x4(ah, smem_u32(&sQh[(mrow + lhf*8 + lr) * ST2 + ks*16 + lnh*8]));
            ldsm_x4(al, smem_u32(&sQl[(mrow + lhf*8 + lr) * ST2 + ks*16 + lnh*8]));
            uint32_t bh[4][2], bl[4][2];
            #pragma unroll
            for (int blk = 0; blk < 2; blk++) {
                uint32_t r4[4];
                ldsm_x4(r4, smem_u32(&sKh[(jcol + blk*16 + lnh*8 + lr) * ST2 + ks*16 + lhf*8]));
                bh[blk*2][0] = r4[0]; bh[blk*2][1] = r4[1];
                bh[blk*2+1][0] = r4[2]; bh[blk*2+1][1] = r4[3];
                ldsm_x4(r4, smem_u32(&sKl[(jcol + blk*16 + lnh*8 + lr) * ST2 + ks*16 + lhf*8]));
                bl[blk*2][0] = r4[0]; bl[blk*2][1] = r4[1];
                bl[blk*2+1][0] = r4[2]; bl[blk*2+1][1] = r4[3];
            }
            #pragma unroll
            for (int t = 0; t < 4; t++) {
                mma_bf16(dA[t], ah, bh[t][0], bh[t][1]);
                mma_bf16(dA[t], ah, bl[t][0], bl[t][1]);
                mma_bf16(dA[t], al, bh[t][0], bh[t][1]);
            }
        }

        // all K reads complete across ALL warps before A overwrites K
        __syncthreads();

        const int row0 = mrow + g;
        const int row1 = row0 + 8;
        #pragma unroll
        for (int t = 0; t < 4; t++) {
            int col = jcol + 8*t + 2*tig;
            float c0 = (col     <= row0) ? dA[t][0] : 0.f;
            float c1 = (col + 1 <= row0) ? dA[t][1] : 0.f;
            float c2 = (col     <= row1) ? dA[t][2] : 0.f;
            float c3 = (col + 1 <= row1) ? dA[t][3] : 0.f;
            __nv_bfloat162 h2, l2;
            splitb(c0, h2.x, l2.x); splitb(c1, h2.y, l2.y);
            *(__nv_bfloat162*)&sAh[row0 * ST2 + col] = h2;
            *(__nv_bfloat162*)&sAl[row0 * ST2 + col] = l2;
            splitb(c2, h2.x, l2.x); splitb(c3, h2.y, l2.y);
            *(__nv_bfloat162*)&sAh[row1 * ST2 + col] = h2;
            *(__nv_bfloat162*)&sAl[row1 * ST2 + col] = l2;
        }
    }
    __syncthreads();

    // ---------------- B-phase ----------------
    {
        const bool has_aux = (w & 1);
        float dO[5][4] = {};

        #pragma unroll
        for (int gsel = 0; gsel < 2; gsel++) {
            const __nv_bfloat16* Aoph = gsel ? sQh : sAh;
            const __nv_bfloat16* Aopl = gsel ? sQl : sAl;
            const __nv_bfloat16* Boph = gsel ? sSh : sVh;
            const __nv_bfloat16* Bopl = gsel ? sSl : sVl;
            #pragma unroll
            for (int ks = 0; ks < 4; ks++) {
                uint32_t ah[4], al[4];
                ldsm_x4(ah, smem_u32(&Aoph[(mrow + lhf*8 + lr) * ST2 + ks*16 + lnh*8]));
                ldsm_x4(al, smem_u32(&Aopl[(mrow + lhf*8 + lr) * ST2 + ks*16 + lnh*8]));
                uint32_t bh[4][2], bl[4][2];
                #pragma unroll
                for (int blk = 0; blk < 2; blk++) {
                    uint32_t r4[4];
                    ldsm_x4t(r4, smem_u32(&Boph[(ks*16 + lhf*8 + lr) * ST2 + jcol + blk*16 + lnh*8]));
                    bh[blk*2][0] = r4[0]; bh[blk*2][1] = r4[1];
                    bh[blk*2+1][0] = r4[2]; bh[blk*2+1][1] = r4[3];
                    ldsm_x4t(r4, smem_u32(&Bopl[(ks*16 + lhf*8 + lr) * ST2 + jcol + blk*16 + lnh*8]));
                    bl[blk*2][0] = r4[0]; bl[blk*2][1] = r4[1];
                    bl[blk*2+1][0] = r4[2]; bl[blk*2+1][1] = r4[3];
                }
                #pragma unroll
                for (int t = 0; t < 4; t++) {
                    mma_bf16(dO[t], ah, bh[t][0], bh[t][1]);
                    mma_bf16(dO[t], ah, bl[t][0], bl[t][1]);
                    mma_bf16(dO[t], al, bh[t][0], bh[t][1]);
                }
                if (has_aux) {
                    uint32_t bxh[2], bxl[2];
                    int r16 = lane & 15;
                    int rr  = (r16 & 7) + ((r16 >> 3) & 1) * 8;
                    ldsm_x2t(bxh, smem_u32(&Boph[(ks*16 + rr) * ST2 + 64]));
                    ldsm_x2t(bxl, smem_u32(&Bopl[(ks*16 + rr) * ST2 + 64]));
                    mma_bf16(dO[4], ah, bxh[0], bxh[1]);
                    mma_bf16(dO[4], ah, bxl[0], bxl[1]);
                    mma_bf16(dO[4], al, bxh[0], bxh[1]);
                }
            }
        }

        const int row0 = mrow + g;
        const int row1 = row0 + 8;

        if (has_aux && tig == 0) {
            sDen[row0] = 1.f / (dO[4][0] + EPSV);
            sDen[row1] = 1.f / (dO[4][2] + EPSV);
        }
        __syncthreads();

        const float inv0 = sDen[row0];
        const float inv1 = sDen[row1];
        #pragma unroll
        for (int t = 0; t < 4; t++) {
            int col = jcol + 8*t + 2*tig;
            *(float2*)&Og[base + (size_t)row0 * DDIM + col] =
                make_float2(dO[t][0] * inv0, dO[t][1] * inv0);
            *(float2*)&Og[base + (size_t)row1 * DDIM + col] =
                make_float2(dO[t][2] * inv1, dO[t][3] * inv1);
        }
    }
}

// ---------------------------------------------------------------------------
extern "C" void kernel_launch(void* const* d_in, const int* in_sizes, int n_in,
                              void* d_out, int out_size) {
    const float* Q = (const float*)d_in[0];
    const float* K = (const float*)d_in[1];
    const float* V = (const float*)d_in[2];
    float* O = (float*)d_out;

    const int SMEM1 = 4 * TILE_ELEMS * 2;                            // 36.9 KB
    const int SMEM3 = 8 * TILE_ELEMS * 2 + 64 * (int)sizeof(float);  // ~74.0 KB

    static int inited = 0;
    if (!inited) {
        cudaFuncSetAttribute(lin_phase1, cudaFuncAttributeMaxDynamicSharedMemorySize, SMEM1);
        cudaFuncSetAttribute(lin_phase3, cudaFuncAttributeMaxDynamicSharedMemorySize, SMEM3);
        inited = 1;
    }

    lin_phase1<<<NB, 256, SMEM1>>>(K, V);
    lin_phase2<<<HNUM * 8, 128>>>();
    lin_phase3<<<NB, 256, SMEM3>>>(Q, K, V, O);
}

// round 15
// speedup vs baseline: 1.0545x; 1.0545x over previous
#include <cuda_runtime.h>
#include <cuda_bf16.h>
#include <cstdint>

#define HNUM 16
#define NSEQ 2048
#define DDIM 64
#define CHK  64
#define NC   (NSEQ / CHK)      // 32 chunks
#define NB   (HNUM * NC)       // 512 (head, chunk) tiles
#define EPSV 1e-6f

// Scratch
__device__ float g_KV[(size_t)NB * DDIM * DDIM];   // per-chunk KV sums (8 MB)
__device__ float g_Kz[(size_t)NB * DDIM];          // per-chunk colsum -> excl prefix
__device__ __align__(16) __nv_bfloat16 g_Sh[(size_t)NB * 4096];  // excl-prefix S hi
__device__ __align__(16) __nv_bfloat16 g_Sl[(size_t)NB * 4096];  // excl-prefix S lo

__device__ __forceinline__ float fmap(float x) {
    return x > 0.f ? x + 1.f : __expf(x);
}

// ---- mma helpers ----
__device__ __forceinline__ uint32_t smem_u32(const void* p) {
    return (uint32_t)__cvta_generic_to_shared(p);
}
__device__ __forceinline__ void ldsm_x4(uint32_t a[4], uint32_t addr) {
    asm volatile("ldmatrix.sync.aligned.m8n8.x4.shared.b16 {%0,%1,%2,%3}, [%4];"
                 : "=r"(a[0]), "=r"(a[1]), "=r"(a[2]), "=r"(a[3]) : "r"(addr));
}
__device__ __forceinline__ void ldsm_x4t(uint32_t a[4], uint32_t addr) {
    asm volatile("ldmatrix.sync.aligned.m8n8.x4.trans.shared.b16 {%0,%1,%2,%3}, [%4];"
                 : "=r"(a[0]), "=r"(a[1]), "=r"(a[2]), "=r"(a[3]) : "r"(addr));
}
__device__ __forceinline__ void ldsm_x2t(uint32_t a[2], uint32_t addr) {
    asm volatile("ldmatrix.sync.aligned.m8n8.x2.trans.shared.b16 {%0,%1}, [%2];"
                 : "=r"(a[0]), "=r"(a[1]) : "r"(addr));
}
__device__ __forceinline__ void mma_bf16(float d[4], const uint32_t a[4],
                                         const uint32_t b0, const uint32_t b1) {
    asm volatile(
        "mma.sync.aligned.m16n8k16.row.col.f32.bf16.bf16.f32 "
        "{%0,%1,%2,%3}, {%4,%5,%6,%7}, {%8,%9}, {%0,%1,%2,%3};"
        : "+f"(d[0]), "+f"(d[1]), "+f"(d[2]), "+f"(d[3])
        : "r"(a[0]), "r"(a[1]), "r"(a[2]), "r"(a[3]), "r"(b0), "r"(b1));
}
__device__ __forceinline__ void splitb(float x, __nv_bfloat16& h, __nv_bfloat16& l) {
    h = __float2bfloat16(x);
    l = __float2bfloat16(x - __bfloat162float(h));
}

#define ST2 72
#define TILE_ELEMS (64 * ST2)

// ---------------------------------------------------------------------------
// Phase 1 (tensor-core): KV[d][e] = sum_m phiK[m][d] V[m][e]; aux col V[:,64]=1
// gives col 64 = Kz[d].  [R11 champion verbatim]
// ---------------------------------------------------------------------------
__global__ void __launch_bounds__(256) lin_phase1(const float* __restrict__ Kg,
                                                  const float* __restrict__ Vg) {
    extern __shared__ __nv_bfloat16 smb1[];
    __nv_bfloat16* sKh = smb1;                     // [m][d] row-major
    __nv_bfloat16* sKl = sKh + TILE_ELEMS;
    __nv_bfloat16* sVh = sKl + TILE_ELEMS;         // [m][e], col64 = 1
    __nv_bfloat16* sVl = sVh + TILE_ELEMS;

    const int tid = threadIdx.x;
    const size_t base = (size_t)blockIdx.x * (CHK * DDIM);

    {
        const int m  = tid >> 2;          // 0..63
        const int c0 = (tid & 3) * 16;
        #pragma unroll
        for (int u = 0; u < 4; u++) {
            int col = c0 + 4 * u;
            float4 k = *(const float4*)(Kg + base + m * DDIM + col);
            float4 v = *(const float4*)(Vg + base + m * DDIM + col);
            float kv[4] = {fmap(k.x), fmap(k.y), fmap(k.z), fmap(k.w)};
            float vv[4] = {v.x, v.y, v.z, v.w};
            #pragma unroll
            for (int p = 0; p < 2; p++) {
                __nv_bfloat162 kh2, kl2, vh2, vl2;
                splitb(kv[2*p],   kh2.x, kl2.x);
                splitb(kv[2*p+1], kh2.y, kl2.y);
                splitb(vv[2*p],   vh2.x, vl2.x);
                splitb(vv[2*p+1], vh2.y, vl2.y);
                *(__nv_bfloat162*)&sKh[m * ST2 + col + 2*p] = kh2;
                *(__nv_bfloat162*)&sKl[m * ST2 + col + 2*p] = kl2;
                *(__nv_bfloat162*)&sVh[m * ST2 + col + 2*p] = vh2;
                *(__nv_bfloat162*)&sVl[m * ST2 + col + 2*p] = vl2;
            }
        }
        if (tid < 64) {                            // aux cols 64..71 of V
            sVh[tid * ST2 + 64] = __float2bfloat16(1.0f);
            sVl[tid * ST2 + 64] = __float2bfloat16(0.0f);
            #pragma unroll
            for (int c = 65; c < 72; c++) {
                sVh[tid * ST2 + c] = __float2bfloat16(0.0f);
                sVl[tid * ST2 + c] = __float2bfloat16(0.0f);
            }
        }
    }
    __syncthreads();

    const int w    = tid >> 5;
    const int lane = tid & 31;
    const int g    = lane >> 2;
    const int tig  = lane & 3;
    const int drow = (w >> 1) * 16;
    const int ecol = (w & 1) * 32;
    const int lr   = lane & 7;
    const int lhf  = (lane >> 3) & 1;
    const int lnh  = lane >> 4;
    const bool has_aux = (w & 1);

    float dO[5][4] = {};
    #pragma unroll
    for (int ks = 0; ks < 4; ks++) {
        uint32_t ah[4], al[4];
        ldsm_x4t(ah, smem_u32(&sKh[(ks*16 + lnh*8 + lr) * ST2 + drow + lhf*8]));
        ldsm_x4t(al, smem_u32(&sKl[(ks*16 + lnh*8 + lr) * ST2 + drow + lhf*8]));
        uint32_t bh[4][2], bl[4][2];
        #pragma unroll
        for (int blk = 0; blk < 2; blk++) {
            uint32_t r4[4];
            ldsm_x4t(r4, smem_u32(&sVh[(ks*16 + lhf*8 + lr) * ST2 + ecol + blk*16 + lnh*8]));
            bh[blk*2][0] = r4[0]; bh[blk*2][1] = r4[1];
            bh[blk*2+1][0] = r4[2]; bh[blk*2+1][1] = r4[3];
            ldsm_x4t(r4, smem_u32(&sVl[(ks*16 + lhf*8 + lr) * ST2 + ecol + blk*16 + lnh*8]));
            bl[blk*2][0] = r4[0]; bl[blk*2][1] = r4[1];
            bl[blk*2+1][0] = r4[2]; bl[blk*2+1][1] = r4[3];
        }
        #pragma unroll
        for (int t = 0; t < 4; t++) {
            mma_bf16(dO[t], ah, bh[t][0], bh[t][1]);
            mma_bf16(dO[t], ah, bl[t][0], bl[t][1]);
            mma_bf16(dO[t], al, bh[t][0], bh[t][1]);
        }
        if (has_aux) {
            uint32_t bxh[2], bxl[2];
            int r16 = lane & 15;
            int rr  = (r16 & 7) + ((r16 >> 3) & 1) * 8;
            ldsm_x2t(bxh, smem_u32(&sVh[(ks*16 + rr) * ST2 + 64]));
            ldsm_x2t(bxl, smem_u32(&sVl[(ks*16 + rr) * ST2 + 64]));
            mma_bf16(dO[4], ah, bxh[0], bxh[1]);
            mma_bf16(dO[4], ah, bxl[0], bxl[1]);
            mma_bf16(dO[4], al, bxh[0], bxh[1]);
        }
    }

    float* kvo = g_KV + (size_t)blockIdx.x * (DDIM * DDIM);
    const int row0 = drow + g;
    const int row1 = row0 + 8;
    #pragma unroll
    for (int t = 0; t < 4; t++) {
        int col = ecol + 8*t + 2*tig;
        *(float2*)&kvo[row0 * DDIM + col] = make_float2(dO[t][0], dO[t][1]);
        *(float2*)&kvo[row1 * DDIM + col] = make_float2(dO[t][2], dO[t][3]);
    }
    if (has_aux && tig == 0) {
        g_Kz[(size_t)blockIdx.x * DDIM + row0] = dO[4][0];
        g_Kz[(size_t)blockIdx.x * DDIM + row1] = dO[4][2];
    }
}

// ---------------------------------------------------------------------------
// Phase 2: exclusive prefix over 32 chunks per head — CHAMPION 512-thread
// scalar form, but writing the prefix PRE-SPLIT to g_Sh/g_Sl (2B coalesced
// stores).  No fp32 writeback.
// ---------------------------------------------------------------------------
__global__ void __launch_bounds__(512) lin_phase2() {
    const int h = blockIdx.x >> 3;
    const int part = blockIdx.x & 7;
    const int idx = part * 512 + threadIdx.x;   // 0..4095 (d*64+e)

    float run = 0.f;
    #pragma unroll
    for (int c = 0; c < NC; c++) {
        const size_t tile = (size_t)(h * NC + c);
        __nv_bfloat16 hh, ll;
        splitb(run, hh, ll);
        g_Sh[tile * 4096 + idx] = hh;
        g_Sl[tile * 4096 + idx] = ll;
        run += g_KV[tile * (DDIM * DDIM) + idx];
    }
    if (part == 0 && threadIdx.x < DDIM) {
        float rz = 0.f;
        #pragma unroll
        for (int c = 0; c < NC; c++) {
            float* p = g_Kz + (size_t)(h * NC + c) * DDIM + threadIdx.x;
            float v = *p;
            *p = rz;
            rz += v;
        }
    }
}

// ---------------------------------------------------------------------------
// Phase 3: tensor-core bf16-split mma, A aliases dead K buffers (74 KB smem).
// S arrives pre-split from phase2 -> prologue is raw uint4 copies.
// ---------------------------------------------------------------------------
__global__ void __launch_bounds__(256) lin_phase3(const float* __restrict__ Qg,
                                                  const float* __restrict__ Kg,
                                                  const float* __restrict__ Vg,
                                                  float* __restrict__ Og) {
    extern __shared__ __nv_bfloat16 smb[];
    __nv_bfloat16* sQh = smb;
    __nv_bfloat16* sQl = sQh + TILE_ELEMS;
    __nv_bfloat16* sKh = sQl + TILE_ELEMS;   // [j][d] row-major; becomes sAh
    __nv_bfloat16* sKl = sKh + TILE_ELEMS;   //                  becomes sAl
    __nv_bfloat16* sVh = sKl + TILE_ELEMS;   // [k][e], col64 = 1
    __nv_bfloat16* sVl = sVh + TILE_ELEMS;
    __nv_bfloat16* sSh = sVl + TILE_ELEMS;   // [d][e], col64 = z
    __nv_bfloat16* sSl = sSh + TILE_ELEMS;
    __nv_bfloat16* sAh = sKh;                // alias (K dead after A-phase)
    __nv_bfloat16* sAl = sKl;                // alias
    float* sDen = (float*)(sSl + TILE_ELEMS);

    const int tid = threadIdx.x;
    const size_t base = (size_t)blockIdx.x * (CHK * DDIM);

    // ---------------- load + fmap + split ----------------
    {
        const int m  = tid >> 2;          // 0..63
        const int c0 = (tid & 3) * 16;
        #pragma unroll
        for (int u = 0; u < 4; u++) {
            int col = c0 + 4 * u;
            float4 q = *(const float4*)(Qg + base + m * DDIM + col);
            float4 k = *(const float4*)(Kg + base + m * DDIM + col);
            float4 v = *(const float4*)(Vg + base + m * DDIM + col);
            float qv[4] = {fmap(q.x), fmap(q.y), fmap(q.z), fmap(q.w)};
            float kv[4] = {fmap(k.x), fmap(k.y), fmap(k.z), fmap(k.w)};
            float vv[4] = {v.x, v.y, v.z, v.w};
            #pragma unroll
            for (int p = 0; p < 2; p++) {
                __nv_bfloat162 qh2, ql2, kh2, kl2, vh2, vl2;
                splitb(qv[2*p],   qh2.x, ql2.x);
                splitb(qv[2*p+1], qh2.y, ql2.y);
                splitb(kv[2*p],   kh2.x, kl2.x);
                splitb(kv[2*p+1], kh2.y, kl2.y);
                splitb(vv[2*p],   vh2.x, vl2.x);
                splitb(vv[2*p+1], vh2.y, vl2.y);
                *(__nv_bfloat162*)&sQh[m * ST2 + col + 2*p] = qh2;
                *(__nv_bfloat162*)&sQl[m * ST2 + col + 2*p] = ql2;
                *(__nv_bfloat162*)&sKh[m * ST2 + col + 2*p] = kh2;
                *(__nv_bfloat162*)&sKl[m * ST2 + col + 2*p] = kl2;
                *(__nv_bfloat162*)&sVh[m * ST2 + col + 2*p] = vh2;
                *(__nv_bfloat162*)&sVl[m * ST2 + col + 2*p] = vl2;
            }
        }
        // S pre-split: raw uint4 copies (512 uint4 per array)
        const uint4* Sh4 = (const uint4*)(g_Sh + (size_t)blockIdx.x * 4096);
        const uint4* Sl4 = (const uint4*)(g_Sl + (size_t)blockIdx.x * 4096);
        #pragma unroll
        for (int s = 0; s < 2; s++) {
            int iu = tid + s * 256;       // 0..511
            uint4 hv = Sh4[iu];
            uint4 lv = Sl4[iu];
            int d = iu >> 3;              // 8 uint4 (= 64 bf16) per row
            int e = (iu & 7) * 8;
            *(uint4*)&sSh[d * ST2 + e] = hv;
            *(uint4*)&sSl[d * ST2 + e] = lv;
        }
        if (tid < 64) {
            float z = g_Kz[(size_t)blockIdx.x * DDIM + tid];
            __nv_bfloat16 zh, zl;
            splitb(z, zh, zl);
            sSh[tid * ST2 + 64] = zh;
            sSl[tid * ST2 + 64] = zl;
            sVh[tid * ST2 + 64] = __float2bfloat16(1.0f);
            sVl[tid * ST2 + 64] = __float2bfloat16(0.0f);
            #pragma unroll
            for (int c = 65; c < 72; c++) {
                sVh[tid * ST2 + c] = __float2bfloat16(0.0f);
                sVl[tid * ST2 + c] = __float2bfloat16(0.0f);
                sSh[tid * ST2 + c] = __float2bfloat16(0.0f);
                sSl[tid * ST2 + c] = __float2bfloat16(0.0f);
            }
        }
    }
    __syncthreads();

    const int w    = tid >> 5;
    const int lane = tid & 31;
    const int g    = lane >> 2;
    const int tig  = lane & 3;
    const int mrow = (w >> 1) * 16;
    const int jcol = (w & 1) * 32;
    const int lr  = lane & 7;
    const int lhf = (lane >> 3) & 1;
    const int lnh = lane >> 4;

    // ---------------- A-phase: A = phiQ phiK^T (K read, then aliased write) ----------------
    {
        float dA[4][4] = {};
        #pragma unroll
        for (int ks = 0; ks < 4; ks++) {
            uint32_t ah[4], al[4];
            ldsm_x4(ah, smem_u32(&sQh[(mrow + lhf*8 + lr) * ST2 + ks*16 + lnh*8]));
            ldsm_x4(al, smem_u32(&sQl[(mrow + lhf*8 + lr) * ST2 + ks*16 + lnh*8]));
            uint32_t bh[4][2], bl[4][2];
            #pragma unroll
            for (int blk = 0; blk < 2; blk++) {
                uint32_t r4[4];
                ldsm_x4(r4, smem_u32(&sKh[(jcol + blk*16 + lnh*8 + lr) * ST2 + ks*16 + lhf*8]));
                bh[blk*2][0] = r4[0]; bh[blk*2][1] = r4[1];
                bh[blk*2+1][0] = r4[2]; bh[blk*2+1][1] = r4[3];
                ldsm_x4(r4, smem_u32(&sKl[(jcol + blk*16 + lnh*8 + lr) * ST2 + ks*16 + lhf*8]));
                bl[blk*2][0] = r4[0]; bl[blk*2][1] = r4[1];
                bl[blk*2+1][0] = r4[2]; bl[blk*2+1][1] = r4[3];
            }
            #pragma unroll
            for (int t = 0; t < 4; t++) {
                mma_bf16(dA[t], ah, bh[t][0], bh[t][1]);
                mma_bf16(dA[t], ah, bl[t][0], bl[t][1]);
                mma_bf16(dA[t], al, bh[t][0], bh[t][1]);
            }
        }

        // all K reads complete across ALL warps before A overwrites K
        __syncthreads();

        const int row0 = mrow + g;
        const int row1 = row0 + 8;
        #pragma unroll
        for (int t = 0; t < 4; t++) {
            int col = jcol + 8*t + 2*tig;
            float c0 = (col     <= row0) ? dA[t][0] : 0.f;
            float c1 = (col + 1 <= row0) ? dA[t][1] : 0.f;
            float c2 = (col     <= row1) ? dA[t][2] : 0.f;
            float c3 = (col + 1 <= row1) ? dA[t][3] : 0.f;
            __nv_bfloat162 h2, l2;
            splitb(c0, h2.x, l2.x); splitb(c1, h2.y, l2.y);
            *(__nv_bfloat162*)&sAh[row0 * ST2 + col] = h2;
            *(__nv_bfloat162*)&sAl[row0 * ST2 + col] = l2;
            splitb(c2, h2.x, l2.x); splitb(c3, h2.y, l2.y);
            *(__nv_bfloat162*)&sAh[row1 * ST2 + col] = h2;
            *(__nv_bfloat162*)&sAl[row1 * ST2 + col] = l2;
        }
    }
    __syncthreads();

    // ---------------- B-phase ----------------
    {
        const bool has_aux = (w & 1);
        float dO[5][4] = {};

        #pragma unroll
        for (int gsel = 0; gsel < 2; gsel++) {
            const __nv_bfloat16* Aoph = gsel ? sQh : sAh;
            const __nv_bfloat16* Aopl = gsel ? sQl : sAl;
            const __nv_bfloat16* Boph = gsel ? sSh : sVh;
            const __nv_bfloat16* Bopl = gsel ? sSl : sVl;
            #pragma unroll
            for (int ks = 0; ks < 4; ks++) {
                uint32_t ah[4], al[4];
                ldsm_x4(ah, smem_u32(&Aoph[(mrow + lhf*8 + lr) * ST2 + ks*16 + lnh*8]));
                ldsm_x4(al, smem_u32(&Aopl[(mrow + lhf*8 + lr) * ST2 + ks*16 + lnh*8]));
                uint32_t bh[4][2], bl[4][2];
                #pragma unroll
                for (int blk = 0; blk < 2; blk++) {
                    uint32_t r4[4];
                    ldsm_x4t(r4, smem_u32(&Boph[(ks*16 + lhf*8 + lr) * ST2 + jcol + blk*16 + lnh*8]));
                    bh[blk*2][0] = r4[0]; bh[blk*2][1] = r4[1];
                    bh[blk*2+1][0] = r4[2]; bh[blk*2+1][1] = r4[3];
                    ldsm_x4t(r4, smem_u32(&Bopl[(ks*16 + lhf*8 + lr) * ST2 + jcol + blk*16 + lnh*8]));
                    bl[blk*2][0] = r4[0]; bl[blk*2][1] = r4[1];
                    bl[blk*2+1][0] = r4[2]; bl[blk*2+1][1] = r4[3];
                }
                #pragma unroll
                for (int t = 0; t < 4; t++) {
                    mma_bf16(dO[t], ah, bh[t][0], bh[t][1]);
                    mma_bf16(dO[t], ah, bl[t][0], bl[t][1]);
                    mma_bf16(dO[t], al, bh[t][0], bh[t][1]);
                }
                if (has_aux) {
                    uint32_t bxh[2], bxl[2];
                    int r16 = lane & 15;
                    int rr  = (r16 & 7) + ((r16 >> 3) & 1) * 8;
                    ldsm_x2t(bxh, smem_u32(&Boph[(ks*16 + rr) * ST2 + 64]));
                    ldsm_x2t(bxl, smem_u32(&Bopl[(ks*16 + rr) * ST2 + 64]));
                    mma_bf16(dO[4], ah, bxh[0], bxh[1]);
                    mma_bf16(dO[4], ah, bxl[0], bxl[1]);
                    mma_bf16(dO[4], al, bxh[0], bxh[1]);
                }
            }
        }

        const int row0 = mrow + g;
        const int row1 = row0 + 8;

        if (has_aux && tig == 0) {
            sDen[row0] = 1.f / (dO[4][0] + EPSV);
            sDen[row1] = 1.f / (dO[4][2] + EPSV);
        }
        __syncthreads();

        const float inv0 = sDen[row0];
        const float inv1 = sDen[row1];
        #pragma unroll
        for (int t = 0; t < 4; t++) {
            int col = jcol + 8*t + 2*tig;
            *(float2*)&Og[base + (size_t)row0 * DDIM + col] =
                make_float2(dO[t][0] * inv0, dO[t][1] * inv0);
            *(float2*)&Og[base + (size_t)row1 * DDIM + col] =
                make_float2(dO[t][2] * inv1, dO[t][3] * inv1);
        }
    }
}

// ---------------------------------------------------------------------------
extern "C" void kernel_launch(void* const* d_in, const int* in_sizes, int n_in,
                              void* d_out, int out_size) {
    const float* Q = (const float*)d_in[0];
    const float* K = (const float*)d_in[1];
    const float* V = (const float*)d_in[2];
    float* O = (float*)d_out;

    const int SMEM1 = 4 * TILE_ELEMS * 2;                            // 36.9 KB
    const int SMEM3 = 8 * TILE_ELEMS * 2 + 64 * (int)sizeof(float);  // ~74.0 KB

    static int inited = 0;
    if (!inited) {
        cudaFuncSetAttribute(lin_phase1, cudaFuncAttributeMaxDynamicSharedMemorySize, SMEM1);
        cudaFuncSetAttribute(lin_phase3, cudaFuncAttributeMaxDynamicSharedMemorySize, SMEM3);
        inited = 1;
    }

    lin_phase1<<<NB, 256, SMEM1>>>(K, V);
    lin_phase2<<<HNUM * 8, 512>>>();
    lin_phase3<<<NB, 256, SMEM3>>>(Q, K, V, O);
}

// round 16
// speedup vs baseline: 1.2604x; 1.1953x over previous
#include <cuda_runtime.h>
#include <cuda_bf16.h>
#include <cstdint>

#define HNUM 16
#define NSEQ 2048
#define DDIM 64
#define CHK  64
#define NC   (NSEQ / CHK)      // 32 chunks
#define NB   (HNUM * NC)       // 512 (head, chunk) tiles
#define EPSV 1e-6f

// Scratch: per-(head,chunk) KV state (64x64) and K feature-sum (64).
__device__ float g_KV[(size_t)NB * DDIM * DDIM];   // 8 MB
__device__ float g_Kz[(size_t)NB * DDIM];          // 128 KB

__device__ __forceinline__ float fmap(float x) {
    return x > 0.f ? x + 1.f : __expf(x);
}

// ---- mma helpers ----
__device__ __forceinline__ uint32_t smem_u32(const void* p) {
    return (uint32_t)__cvta_generic_to_shared(p);
}
__device__ __forceinline__ void ldsm_x4(uint32_t a[4], uint32_t addr) {
    asm volatile("ldmatrix.sync.aligned.m8n8.x4.shared.b16 {%0,%1,%2,%3}, [%4];"
                 : "=r"(a[0]), "=r"(a[1]), "=r"(a[2]), "=r"(a[3]) : "r"(addr));
}
__device__ __forceinline__ void ldsm_x4t(uint32_t a[4], uint32_t addr) {
    asm volatile("ldmatrix.sync.aligned.m8n8.x4.trans.shared.b16 {%0,%1,%2,%3}, [%4];"
                 : "=r"(a[0]), "=r"(a[1]), "=r"(a[2]), "=r"(a[3]) : "r"(addr));
}
__device__ __forceinline__ void ldsm_x2t(uint32_t a[2], uint32_t addr) {
    asm volatile("ldmatrix.sync.aligned.m8n8.x2.trans.shared.b16 {%0,%1}, [%2];"
                 : "=r"(a[0]), "=r"(a[1]) : "r"(addr));
}
__device__ __forceinline__ void mma_bf16(float d[4], const uint32_t a[4],
                                         const uint32_t b0, const uint32_t b1) {
    asm volatile(
        "mma.sync.aligned.m16n8k16.row.col.f32.bf16.bf16.f32 "
        "{%0,%1,%2,%3}, {%4,%5,%6,%7}, {%8,%9}, {%0,%1,%2,%3};"
        : "+f"(d[0]), "+f"(d[1]), "+f"(d[2]), "+f"(d[3])
        : "r"(a[0]), "r"(a[1]), "r"(a[2]), "r"(a[3]), "r"(b0), "r"(b1));
}
__device__ __forceinline__ void splitb(float x, __nv_bfloat16& h, __nv_bfloat16& l) {
    h = __float2bfloat16(x);
    l = __float2bfloat16(x - __bfloat162float(h));
}

#define ST2 72
#define TILE_ELEMS (64 * ST2)

// ---------------------------------------------------------------------------
// Phase 1 (tensor-core): KV[d][e] = sum_m phiK[m][d] V[m][e]; aux col V[:,64]=1
// gives col 64 = Kz[d].  [R11 champion verbatim]
// ---------------------------------------------------------------------------
__global__ void __launch_bounds__(256) lin_phase1(const float* __restrict__ Kg,
                                                  const float* __restrict__ Vg) {
    extern __shared__ __nv_bfloat16 smb1[];
    __nv_bfloat16* sKh = smb1;                     // [m][d] row-major
    __nv_bfloat16* sKl = sKh + TILE_ELEMS;
    __nv_bfloat16* sVh = sKl + TILE_ELEMS;         // [m][e], col64 = 1
    __nv_bfloat16* sVl = sVh + TILE_ELEMS;

    const int tid = threadIdx.x;
    const size_t base = (size_t)blockIdx.x * (CHK * DDIM);

    {
        const int m  = tid >> 2;          // 0..63
        const int c0 = (tid & 3) * 16;
        #pragma unroll
        for (int u = 0; u < 4; u++) {
            int col = c0 + 4 * u;
            float4 k = *(const float4*)(Kg + base + m * DDIM + col);
            float4 v = *(const float4*)(Vg + base + m * DDIM + col);
            float kv[4] = {fmap(k.x), fmap(k.y), fmap(k.z), fmap(k.w)};
            float vv[4] = {v.x, v.y, v.z, v.w};
            #pragma unroll
            for (int p = 0; p < 2; p++) {
                __nv_bfloat162 kh2, kl2, vh2, vl2;
                splitb(kv[2*p],   kh2.x, kl2.x);
                splitb(kv[2*p+1], kh2.y, kl2.y);
                splitb(vv[2*p],   vh2.x, vl2.x);
                splitb(vv[2*p+1], vh2.y, vl2.y);
                *(__nv_bfloat162*)&sKh[m * ST2 + col + 2*p] = kh2;
                *(__nv_bfloat162*)&sKl[m * ST2 + col + 2*p] = kl2;
                *(__nv_bfloat162*)&sVh[m * ST2 + col + 2*p] = vh2;
                *(__nv_bfloat162*)&sVl[m * ST2 + col + 2*p] = vl2;
            }
        }
        if (tid < 64) {                            // aux cols 64..71 of V
            sVh[tid * ST2 + 64] = __float2bfloat16(1.0f);
            sVl[tid * ST2 + 64] = __float2bfloat16(0.0f);
            #pragma unroll
            for (int c = 65; c < 72; c++) {
                sVh[tid * ST2 + c] = __float2bfloat16(0.0f);
                sVl[tid * ST2 + c] = __float2bfloat16(0.0f);
            }
        }
    }
    __syncthreads();

    const int w    = tid >> 5;
    const int lane = tid & 31;
    const int g    = lane >> 2;
    const int tig  = lane & 3;
    const int drow = (w >> 1) * 16;
    const int ecol = (w & 1) * 32;
    const int lr   = lane & 7;
    const int lhf  = (lane >> 3) & 1;
    const int lnh  = lane >> 4;
    const bool has_aux = (w & 1);

    float dO[5][4] = {};
    #pragma unroll
    for (int ks = 0; ks < 4; ks++) {
        uint32_t ah[4], al[4];
        ldsm_x4t(ah, smem_u32(&sKh[(ks*16 + lnh*8 + lr) * ST2 + drow + lhf*8]));
        ldsm_x4t(al, smem_u32(&sKl[(ks*16 + lnh*8 + lr) * ST2 + drow + lhf*8]));
        uint32_t bh[4][2], bl[4][2];
        #pragma unroll
        for (int blk = 0; blk < 2; blk++) {
            uint32_t r4[4];
            ldsm_x4t(r4, smem_u32(&sVh[(ks*16 + lhf*8 + lr) * ST2 + ecol + blk*16 + lnh*8]));
            bh[blk*2][0] = r4[0]; bh[blk*2][1] = r4[1];
            bh[blk*2+1][0] = r4[2]; bh[blk*2+1][1] = r4[3];
            ldsm_x4t(r4, smem_u32(&sVl[(ks*16 + lhf*8 + lr) * ST2 + ecol + blk*16 + lnh*8]));
            bl[blk*2][0] = r4[0]; bl[blk*2][1] = r4[1];
            bl[blk*2+1][0] = r4[2]; bl[blk*2+1][1] = r4[3];
        }
        #pragma unroll
        for (int t = 0; t < 4; t++) {
            mma_bf16(dO[t], ah, bh[t][0], bh[t][1]);
            mma_bf16(dO[t], ah, bl[t][0], bl[t][1]);
            mma_bf16(dO[t], al, bh[t][0], bh[t][1]);
        }
        if (has_aux) {
            uint32_t bxh[2], bxl[2];
            int r16 = lane & 15;
            int rr  = (r16 & 7) + ((r16 >> 3) & 1) * 8;
            ldsm_x2t(bxh, smem_u32(&sVh[(ks*16 + rr) * ST2 + 64]));
            ldsm_x2t(bxl, smem_u32(&sVl[(ks*16 + rr) * ST2 + 64]));
            mma_bf16(dO[4], ah, bxh[0], bxh[1]);
            mma_bf16(dO[4], ah, bxl[0], bxl[1]);
            mma_bf16(dO[4], al, bxh[0], bxh[1]);
        }
    }

    float* kvo = g_KV + (size_t)blockIdx.x * (DDIM * DDIM);
    const int row0 = drow + g;
    const int row1 = row0 + 8;
    #pragma unroll
    for (int t = 0; t < 4; t++) {
        int col = ecol + 8*t + 2*tig;
        *(float2*)&kvo[row0 * DDIM + col] = make_float2(dO[t][0], dO[t][1]);
        *(float2*)&kvo[row1 * DDIM + col] = make_float2(dO[t][2], dO[t][3]);
    }
    if (has_aux && tig == 0) {
        g_Kz[(size_t)blockIdx.x * DDIM + row0] = dO[4][0];
        g_Kz[(size_t)blockIdx.x * DDIM + row1] = dO[4][2];
    }
}

// ---------------------------------------------------------------------------
// Phase 2: exclusive prefix over 32 chunks per head. [champion verbatim]
// ---------------------------------------------------------------------------
__global__ void __launch_bounds__(512) lin_phase2() {
    const int h = blockIdx.x >> 3;
    const int part = blockIdx.x & 7;
    const int idx = part * 512 + threadIdx.x;

    float run = 0.f;
    #pragma unroll
    for (int c = 0; c < NC; c++) {
        float* p = g_KV + ((size_t)(h * NC + c)) * (DDIM * DDIM) + idx;
        float v = *p;
        *p = run;
        run += v;
    }
    if (part == 0 && threadIdx.x < DDIM) {
        float rz = 0.f;
        #pragma unroll
        for (int c = 0; c < NC; c++) {
            float* p = g_Kz + (size_t)(h * NC + c) * DDIM + threadIdx.x;
            float v = *p;
            *p = rz;
            rz += v;
        }
    }
}

// ---------------------------------------------------------------------------
// Phase 3: tensor-core bf16-split mma, A aliases dead K buffers (74 KB smem).
// THIS ROUND: causal work-skipping — (1) A-phase warps whose 16x32 block is
// entirely above the diagonal (w=1,3) skip their GEMM; (2) B-phase A@V k-loop
// truncated per warp to ks <= w>>1 (A is zero beyond the diagonal).
// All skipped contributions are exact zeros -> bit-identical output.
// ---------------------------------------------------------------------------
__global__ void __launch_bounds__(256) lin_phase3(const float* __restrict__ Qg,
                                                  const float* __restrict__ Kg,
                                                  const float* __restrict__ Vg,
                                                  float* __restrict__ Og) {
    extern __shared__ __nv_bfloat16 smb[];
    __nv_bfloat16* sQh = smb;
    __nv_bfloat16* sQl = sQh + TILE_ELEMS;
    __nv_bfloat16* sKh = sQl + TILE_ELEMS;   // [j][d] row-major; becomes sAh
    __nv_bfloat16* sKl = sKh + TILE_ELEMS;   //                  becomes sAl
    __nv_bfloat16* sVh = sKl + TILE_ELEMS;   // [k][e], col64 = 1
    __nv_bfloat16* sVl = sVh + TILE_ELEMS;
    __nv_bfloat16* sSh = sVl + TILE_ELEMS;   // [d][e], col64 = z
    __nv_bfloat16* sSl = sSh + TILE_ELEMS;
    __nv_bfloat16* sAh = sKh;                // alias (K dead after A-phase)
    __nv_bfloat16* sAl = sKl;                // alias
    float* sDen = (float*)(sSl + TILE_ELEMS);

    const int tid = threadIdx.x;
    const size_t base = (size_t)blockIdx.x * (CHK * DDIM);

    // ---------------- load + fmap + split ----------------
    {
        const int m  = tid >> 2;          // 0..63
        const int c0 = (tid & 3) * 16;
        #pragma unroll
        for (int u = 0; u < 4; u++) {
            int col = c0 + 4 * u;
            float4 q = *(const float4*)(Qg + base + m * DDIM + col);
            float4 k = *(const float4*)(Kg + base + m * DDIM + col);
            float4 v = *(const float4*)(Vg + base + m * DDIM + col);
            float qv[4] = {fmap(q.x), fmap(q.y), fmap(q.z), fmap(q.w)};
            float kv[4] = {fmap(k.x), fmap(k.y), fmap(k.z), fmap(k.w)};
            float vv[4] = {v.x, v.y, v.z, v.w};
            #pragma unroll
            for (int p = 0; p < 2; p++) {
                __nv_bfloat162 qh2, ql2, kh2, kl2, vh2, vl2;
                splitb(qv[2*p],   qh2.x, ql2.x);
                splitb(qv[2*p+1], qh2.y, ql2.y);
                splitb(kv[2*p],   kh2.x, kl2.x);
                splitb(kv[2*p+1], kh2.y, kl2.y);
                splitb(vv[2*p],   vh2.x, vl2.x);
                splitb(vv[2*p+1], vh2.y, vl2.y);
                *(__nv_bfloat162*)&sQh[m * ST2 + col + 2*p] = qh2;
                *(__nv_bfloat162*)&sQl[m * ST2 + col + 2*p] = ql2;
                *(__nv_bfloat162*)&sKh[m * ST2 + col + 2*p] = kh2;
                *(__nv_bfloat162*)&sKl[m * ST2 + col + 2*p] = kl2;
                *(__nv_bfloat162*)&sVh[m * ST2 + col + 2*p] = vh2;
                *(__nv_bfloat162*)&sVl[m * ST2 + col + 2*p] = vl2;
            }
        }
        const float4* Sg4 = (const float4*)(g_KV + (size_t)blockIdx.x * (DDIM * DDIM));
        #pragma unroll
        for (int s = 0; s < 4; s++) {
            int i4 = tid + s * 256;
            int d  = i4 >> 4;
            int e0 = (i4 & 15) * 4;
            float4 sv = Sg4[i4];
            float ss[4] = {sv.x, sv.y, sv.z, sv.w};
            #pragma unroll
            for (int p = 0; p < 2; p++) {
                __nv_bfloat162 h2, l2;
                splitb(ss[2*p],   h2.x, l2.x);
                splitb(ss[2*p+1], h2.y, l2.y);
                *(__nv_bfloat162*)&sSh[d * ST2 + e0 + 2*p] = h2;
                *(__nv_bfloat162*)&sSl[d * ST2 + e0 + 2*p] = l2;
            }
        }
        if (tid < 64) {
            float z = g_Kz[(size_t)blockIdx.x * DDIM + tid];
            __nv_bfloat16 zh, zl;
            splitb(z, zh, zl);
            sSh[tid * ST2 + 64] = zh;
            sSl[tid * ST2 + 64] = zl;
            sVh[tid * ST2 + 64] = __float2bfloat16(1.0f);
            sVl[tid * ST2 + 64] = __float2bfloat16(0.0f);
            #pragma unroll
            for (int c = 65; c < 72; c++) {
                sVh[tid * ST2 + c] = __float2bfloat16(0.0f);
                sVl[tid * ST2 + c] = __float2bfloat16(0.0f);
                sSh[tid * ST2 + c] = __float2bfloat16(0.0f);
                sSl[tid * ST2 + c] = __float2bfloat16(0.0f);
            }
        }
    }
    __syncthreads();

    const int w    = tid >> 5;
    const int lane = tid & 31;
    const int g    = lane >> 2;
    const int tig  = lane & 3;
    const int mrow = (w >> 1) * 16;
    const int jcol = (w & 1) * 32;
    const int lr  = lane & 7;
    const int lhf = (lane >> 3) & 1;
    const int lnh = lane >> 4;

    // ---------------- A-phase: A = phiQ phiK^T (K read, then aliased write) ----------------
    {
        float dA[4][4] = {};
        // Skip GEMM entirely for warps whose block is fully above the diagonal
        // (jcol > mrow+15): warps 1 and 3.  Their dA stays zero, stores below
        // write the (masked) zeros.
        if (jcol <= mrow + 15) {
            #pragma unroll
            for (int ks = 0; ks < 4; ks++) {
                uint32_t ah[4], al[4];
                ldsm_x4(ah, smem_u32(&sQh[(mrow + lhf*8 + lr) * ST2 + ks*16 + lnh*8]));
                ldsm_x4(al, smem_u32(&sQl[(mrow + lhf*8 + lr) * ST2 + ks*16 + lnh*8]));
                uint32_t bh[4][2], bl[4][2];
                #pragma unroll
                for (int blk = 0; blk < 2; blk++) {
                    uint32_t r4[4];
                    ldsm_x4(r4, smem_u32(&sKh[(jcol + blk*16 + lnh*8 + lr) * ST2 + ks*16 + lhf*8]));
                    bh[blk*2][0] = r4[0]; bh[blk*2][1] = r4[1];
                    bh[blk*2+1][0] = r4[2]; bh[blk*2+1][1] = r4[3];
                    ldsm_x4(r4, smem_u32(&sKl[(jcol + blk*16 + lnh*8 + lr) * ST2 + ks*16 + lhf*8]));
                    bl[blk*2][0] = r4[0]; bl[blk*2][1] = r4[1];
                    bl[blk*2+1][0] = r4[2]; bl[blk*2+1][1] = r4[3];
                }
                #pragma unroll
                for (int t = 0; t < 4; t++) {
                    mma_bf16(dA[t], ah, bh[t][0], bh[t][1]);
                    mma_bf16(dA[t], ah, bl[t][0], bl[t][1]);
                    mma_bf16(dA[t], al, bh[t][0], bh[t][1]);
                }
            }
        }

        // all K reads complete across ALL warps before A overwrites K
        __syncthreads();

        const int row0 = mrow + g;
        const int row1 = row0 + 8;
        #pragma unroll
        for (int t = 0; t < 4; t++) {
            int col = jcol + 8*t + 2*tig;
            float c0 = (col     <= row0) ? dA[t][0] : 0.f;
            float c1 = (col + 1 <= row0) ? dA[t][1] : 0.f;
            float c2 = (col     <= row1) ? dA[t][2] : 0.f;
            float c3 = (col + 1 <= row1) ? dA[t][3] : 0.f;
            __nv_bfloat162 h2, l2;
            splitb(c0, h2.x, l2.x); splitb(c1, h2.y, l2.y);
            *(__nv_bfloat162*)&sAh[row0 * ST2 + col] = h2;
            *(__nv_bfloat162*)&sAl[row0 * ST2 + col] = l2;
            splitb(c2, h2.x, l2.x); splitb(c3, h2.y, l2.y);
            *(__nv_bfloat162*)&sAh[row1 * ST2 + col] = h2;
            *(__nv_bfloat162*)&sAl[row1 * ST2 + col] = l2;
        }
    }
    __syncthreads();

    // ---------------- B-phase ----------------
    {
        const bool has_aux = (w & 1);
        const int ks_max0 = (w >> 1) + 1;   // A@V: A[m][k]=0 for k > mrow+15
        float dO[5][4] = {};

        #pragma unroll
        for (int gsel = 0; gsel < 2; gsel++) {
            const __nv_bfloat16* Aoph = gsel ? sQh : sAh;
            const __nv_bfloat16* Aopl = gsel ? sQl : sAl;
            const __nv_bfloat16* Boph = gsel ? sSh : sVh;
            const __nv_bfloat16* Bopl = gsel ? sSl : sVl;
            #pragma unroll
            for (int ks = 0; ks < 4; ks++) {
                if (gsel == 0 && ks >= ks_max0) continue;   // warp-uniform skip
                uint32_t ah[4], al[4];
                ldsm_x4(ah, smem_u32(&Aoph[(mrow + lhf*8 + lr) * ST2 + ks*16 + lnh*8]));
                ldsm_x4(al, smem_u32(&Aopl[(mrow + lhf*8 + lr) * ST2 + ks*16 + lnh*8]));
                uint32_t bh[4][2], bl[4][2];
                #pragma unroll
                for (int blk = 0; blk < 2; blk++) {
                    uint32_t r4[4];
                    ldsm_x4t(r4, smem_u32(&Boph[(ks*16 + lhf*8 + lr) * ST2 + jcol + blk*16 + lnh*8]));
                    bh[blk*2][0] = r4[0]; bh[blk*2][1] = r4[1];
                    bh[blk*2+1][0] = r4[2]; bh[blk*2+1][1] = r4[3];
                    ldsm_x4t(r4, smem_u32(&Bopl[(ks*16 + lhf*8 + lr) * ST2 + jcol + blk*16 + lnh*8]));
                    bl[blk*2][0] = r4[0]; bl[blk*2][1] = r4[1];
                    bl[blk*2+1][0] = r4[2]; bl[blk*2+1][1] = r4[3];
                }
                #pragma unroll
                for (int t = 0; t < 4; t++) {
                    mma_bf16(dO[t], ah, bh[t][0], bh[t][1]);
                    mma_bf16(dO[t], ah, bl[t][0], bl[t][1]);
                    mma_bf16(dO[t], al, bh[t][0], bh[t][1]);
                }
                if (has_aux) {
                    uint32_t bxh[2], bxl[2];
                    int r16 = lane & 15;
                    int rr  = (r16 & 7) + ((r16 >> 3) & 1) * 8;
                    ldsm_x2t(bxh, smem_u32(&Boph[(ks*16 + rr) * ST2 + 64]));
                    ldsm_x2t(bxl, smem_u32(&Bopl[(ks*16 + rr) * ST2 + 64]));
                    mma_bf16(dO[4], ah, bxh[0], bxh[1]);
                    mma_bf16(dO[4], ah, bxl[0], bxl[1]);
                    mma_bf16(dO[4], al, bxh[0], bxh[1]);
                }
            }
        }

        const int row0 = mrow + g;
        const int row1 = row0 + 8;

        if (has_aux && tig == 0) {
            sDen[row0] = 1.f / (dO[4][0] + EPSV);
            sDen[row1] = 1.f / (dO[4][2] + EPSV);
        }
        __syncthreads();

        const float inv0 = sDen[row0];
        const float inv1 = sDen[row1];
        #pragma unroll
        for (int t = 0; t < 4; t++) {
            int col = jcol + 8*t + 2*tig;
            *(float2*)&Og[base + (size_t)row0 * DDIM + col] =
                make_float2(dO[t][0] * inv0, dO[t][1] * inv0);
            *(float2*)&Og[base + (size_t)row1 * DDIM + col] =
                make_float2(dO[t][2] * inv1, dO[t][3] * inv1);
        }
    }
}

// ---------------------------------------------------------------------------
extern "C" void kernel_launch(void* const* d_in, const int* in_sizes, int n_in,
                              void* d_out, int out_size) {
    const float* Q = (const float*)d_in[0];
    const float* K = (const float*)d_in[1];
    const float* V = (const float*)d_in[2];
    float* O = (float*)d_out;

    const int SMEM1 = 4 * TILE_ELEMS * 2;                            // 36.9 KB
    const int SMEM3 = 8 * TILE_ELEMS * 2 + 64 * (int)sizeof(float);  // ~74.0 KB

    static int inited = 0;
    if (!inited) {
        cudaFuncSetAttribute(lin_phase1, cudaFuncAttributeMaxDynamicSharedMemorySize, SMEM1);
        cudaFuncSetAttribute(lin_phase3, cudaFuncAttributeMaxDynamicSharedMemorySize, SMEM3);
        inited = 1;
    }

    lin_phase1<<<NB, 256, SMEM1>>>(K, V);
    lin_phase2<<<HNUM * 8, 512>>>();
    lin_phase3<<<NB, 256, SMEM3>>>(Q, K, V, O);
}